// round 17
// baseline (speedup 1.0000x reference)
#include <cuda_runtime.h>

// VanillaRNN, v14: two-kernel split, both halves rebuilt.
//   K1: xproj = x @ W_hx^T -- col-per-thread, NO reduction tree, broadcast x,
//       warp-coalesced stores. 2048 CTAs x 256 rows.
//   K2: h = tanh(xp_t + W_hh h) -- v13 chassis but cols=8 per thread (v11's
//       proven select-free 4-stage butterfly), halving LDS per step.
// B=1024, T=512, I=64, H=128, O=10.

#define HDIM 128
#define IDIM 64
#define TSTEPS 512
#define BATCH 1024
#define ODIM 10

// 256 MB fp32 scratch for the x-projection
__device__ float g_xproj[(size_t)BATCH * TSTEPS * HDIM];

__device__ __forceinline__ unsigned long long ffma2(unsigned long long a,
                                                    unsigned long long b,
                                                    unsigned long long c) {
    unsigned long long d;
    asm("fma.rn.f32x2 %0, %1, %2, %3;" : "=l"(d) : "l"(a), "l"(b), "l"(c));
    return d;
}

__device__ __forceinline__ unsigned long long packf2(float lo, float hi) {
    return ((unsigned long long)__float_as_uint(hi) << 32) |
           (unsigned long long)__float_as_uint(lo);
}

__device__ __forceinline__ float sum2(unsigned long long a) {
    return __uint_as_float((unsigned)a) + __uint_as_float((unsigned)(a >> 32));
}

__device__ __forceinline__ float tanh_fast(float z) {
    float r;
    asm("tanh.approx.f32 %0, %1;" : "=f"(r) : "f"(z));
    return r;
}

// ============================================================================
// Kernel 1: xproj = x @ W_hx^T   (M = 524288, N = 128, K = 64)
// Thread = one output column (full K=64 weights in 32 ULL regs) x 4 rows per
// 8-row chunk. x rows broadcast from smem (whole-warp same-address LDS).
// No shuffles, no tree. STG.32 coalesced across the warp's 32 columns.
// ============================================================================

#define K1_GRID 2048
#define K1_ROWS_PER_CTA 256
#define K1_CHUNK 8
#define K1_CHUNKS 32

__global__ void __launch_bounds__(256, 2)
xproj_kernel(const float* __restrict__ x,
             const float* __restrict__ W_hx) {
    __shared__ __align__(16) float xs[2][K1_CHUNK][IDIM];   // 4 KB

    const int tid  = threadIdx.x;
    const int col  = tid & 127;
    const int half = tid >> 7;          // rows 4*half .. 4*half+3 of each chunk

    // full weight row for this column: 64 floats = 32 packed f32x2
    unsigned long long w[32];
#pragma unroll
    for (int j = 0; j < 32; j++)
        w[j] = packf2(W_hx[col * IDIM + 2 * j], W_hx[col * IDIM + 2 * j + 1]);

    const size_t rbase = (size_t)blockIdx.x * K1_ROWS_PER_CTA;

    // loader: tid<128 each load one float4 of the 8x64 chunk
    const int  lrow   = tid >> 4;       // 0..7 (valid when tid<128)
    const int  c4     = (tid & 15) * 4;
    const bool loader = (tid < 128);

    if (loader)
        *(float4*)&xs[0][lrow & 7][c4] =
            *(const float4*)(x + (rbase + (lrow & 7)) * IDIM + c4);
    __syncthreads();

    int p = 0;
    for (int chunk = 0; chunk < K1_CHUNKS; chunk++) {
        float4 xn;
        if (loader && chunk + 1 < K1_CHUNKS)
            xn = *(const float4*)(
                x + (rbase + (size_t)(chunk + 1) * K1_CHUNK + (lrow & 7)) * IDIM + c4);

        const size_t r0 = rbase + (size_t)chunk * K1_CHUNK;

#pragma unroll
        for (int r = 0; r < 4; r++) {
            const int m = half * 4 + r;
            const ulonglong2* px = (const ulonglong2*)&xs[p][m][0];
            unsigned long long a0 = 0ull, a1 = 0ull;
#pragma unroll
            for (int i = 0; i < 16; i++) {
                ulonglong2 v = px[i];                 // broadcast LDS.128
                a0 = ffma2(v.x, w[2 * i], a0);
                a1 = ffma2(v.y, w[2 * i + 1], a1);
            }
            // coalesced: warp = 32 consecutive cols of one row
            g_xproj[(r0 + m) * HDIM + col] = sum2(a0) + sum2(a1);
        }

        if (loader && chunk + 1 < K1_CHUNKS)
            *(float4*)&xs[p ^ 1][lrow & 7][c4] = xn;
        __syncthreads();
        p ^= 1;
    }
}

// ============================================================================
// Kernel 2: recurrence, cols=8 per thread (v11 tree), k=128.
// g = warp*2 + (lane&1) in [0,16): col group, 8 cols {g+16*cperm[c]};
// seg = lane>>1 in [0,16): 8-wide h-k segment. Per thread per step:
// 8 LDS.128 (was 16), 128 FFMA2, 22 shfl. Select-free butterfly:
// xor2 (rows 4->2), xor4 (rows 2->1), xor8 (cols 8->4), xor16 (cols 4->2).
// Segment stride 12 floats (48B, 16B-aligned bases).
// ============================================================================

#define ROWS 4
#define NTHREADS 256
#define SEGF 8
#define SEGP 12
#define RSTRIDE 192        // 16*12
#define XPSTR 132
#define GRID 256

__device__ __forceinline__ int physh(int k) {
    return (k >> 3) * SEGP + (k & 7);
}

// one row's 8-k slice (2 LDS.128) x 8 permuted cols = 32 FFMA2
__device__ __forceinline__ void row_acc8(const float* __restrict__ rowseg,
                                         const unsigned long long w[8][4],
                                         float sv[8]) {
    const ulonglong2* pp = (const ulonglong2*)rowseg;
    ulonglong2 v0 = pp[0], v1 = pp[1];
    unsigned long long a[8];
#pragma unroll
    for (int c = 0; c < 8; c++) a[c] = ffma2(v0.x, w[c][0], 0ull);
#pragma unroll
    for (int c = 0; c < 8; c++) a[c] = ffma2(v0.y, w[c][1], a[c]);
#pragma unroll
    for (int c = 0; c < 8; c++) a[c] = ffma2(v1.x, w[c][2], a[c]);
#pragma unroll
    for (int c = 0; c < 8; c++) a[c] = ffma2(v1.y, w[c][3], a[c]);
#pragma unroll
    for (int c = 0; c < 8; c++) sv[c] = sum2(a[c]);
}

__global__ void __launch_bounds__(NTHREADS, 2)
rnn_fused_kernel(const float* __restrict__ W_hh,
                 const float* __restrict__ b_hh,
                 const float* __restrict__ W_ph,
                 const float* __restrict__ b_ph,
                 float* __restrict__ out) {
    __shared__ __align__(16) float buf[2][ROWS][RSTRIDE];   // h state
    __shared__ __align__(16) float xps[2][ROWS][XPSTR];     // staged xproj

    const int tid  = threadIdx.x;
    const int lane = tid & 31;
    const int warp = tid >> 5;
    const int g    = warp * 2 + (lane & 1);   // col group 0..15
    const int seg  = lane >> 1;               // k-segment 0..15
    const int b0r  = blockIdx.x * ROWS;

    const int sb0 = seg & 1, sb1 = (seg >> 1) & 1,
              sb2 = (seg >> 2) & 1, sb3 = (seg >> 3) & 1;

    // per-thread permuted column order (stage-2/3 select elimination; v11)
    int cperm[8];
#pragma unroll
    for (int j = 0; j < 8; j++) {
        const int j0 = j & 1, j1 = (j >> 1) & 1, j2 = (j >> 2) & 1;
        cperm[j] = 4 * (j2 ? (1 - sb2) : sb2) + 2 * (j1 ? (1 - sb3) : sb3) + j0;
    }

    // weights: W_hh, 8 permuted cols x 4 packed f32x2 (8 k each) = 64 regs
    unsigned long long w[8][4];
#pragma unroll
    for (int c = 0; c < 8; c++) {
        const int o = g + 16 * cperm[c];
#pragma unroll
        for (int j = 0; j < 4; j++) {
            const int k0 = seg * SEGF + 2 * j;
            w[c][j] = packf2(W_hh[o * HDIM + k0], W_hh[o * HDIM + k0 + 1]);
        }
    }

    // per-thread row order (stage-0/1 select elimination)
    const int rKA = sb1 + 2 * sb0;
    const int rSA = sb1 + 2 * (1 - sb0);
    const int rKB = (1 - sb1) + 2 * sb0;
    const int rSB = (1 - sb1) + 2 * (1 - sb0);
    const int segoff = seg * SEGP;
    const int oKA = rKA * RSTRIDE + segoff;
    const int oSA = rSA * RSTRIDE + segoff;
    const int oKB = rKB * RSTRIDE + segoff;
    const int oSB = rSB * RSTRIDE + segoff;

    const int mstar = 2 * sb0 + sb1;
    const int of0 = g + 16 * cperm[0];        // cperm[1] = cperm[0]+1 -> of0+16
    const int of1 = of0 + 16;
    const float bb0 = b_hh[of0];
    const float bb1 = b_hh[of1];
    const int ph0 = physh(of0);
    const int ph1 = physh(of1);
    const int xq0 = mstar * XPSTR + of0;
    const int xq1 = mstar * XPSTR + of1;

    // zero h buffers (h0 = 0)
    for (int i = tid; i < 2 * ROWS * RSTRIDE; i += NTHREADS)
        ((float*)buf)[i] = 0.0f;

    // xp loader: tid<128, row xr = tid>>5, float4 chunk c4 = (tid&31)*4
    const int xr  = (tid >> 5) & 3;
    const int c4  = (tid & 31) * 4;
    const bool loader = (tid < 128);
    const float* xprow = g_xproj + ((size_t)(b0r + xr) * TSTEPS) * HDIM;

    if (loader)
        *(float4*)&xps[0][xr][c4] = *(const float4*)(xprow + c4);   // xp_0
    __syncthreads();

    int p = 0;
    for (int t = 0; t < TSTEPS; t++) {
        float4 xn;
        if (loader) {
            const int tn = (t + 1 < TSTEPS) ? t + 1 : TSTEPS - 1;
            xn = *(const float4*)(xprow + (size_t)tn * HDIM + c4);
        }

        // fetch this lane's xp pair early (independent of h chain)
        const float xp0 = xps[p][0][xq0];
        const float xp1 = xps[p][0][xq1];

        const float* base = &buf[p][0][0];

        // ---- stage 0 (xor 2): rows 4 -> 2, folded after each pair
        float ra[8];
        {
            float aK[8], aS[8];
            row_acc8(base + oKA, w, aK);
            row_acc8(base + oSA, w, aS);
#pragma unroll
            for (int c = 0; c < 8; c++)
                ra[c] = aK[c] + __shfl_xor_sync(0xffffffffu, aS[c], 2);
        }
        float rb[8];
        {
            float aK[8], aS[8];
            row_acc8(base + oKB, w, aK);
            row_acc8(base + oSB, w, aS);
#pragma unroll
            for (int c = 0; c < 8; c++)
                rb[c] = aK[c] + __shfl_xor_sync(0xffffffffu, aS[c], 2);
        }

        // ---- stage 1 (xor 4): rows 2 -> 1
        float rc[8];
#pragma unroll
        for (int c = 0; c < 8; c++)
            rc[c] = ra[c] + __shfl_xor_sync(0xffffffffu, rb[c], 4);

        // ---- stage 2 (xor 8): cols 8 -> 4
        float rd[4];
#pragma unroll
        for (int c = 0; c < 4; c++)
            rd[c] = rc[c] + __shfl_xor_sync(0xffffffffu, rc[c + 4], 8);

        // ---- stage 3 (xor 16): cols 4 -> 2
        const float f0 = rd[0] + __shfl_xor_sync(0xffffffffu, rd[2], 16);
        const float f1 = rd[1] + __shfl_xor_sync(0xffffffffu, rd[3], 16);

        const int q = p ^ 1;
        buf[q][mstar][ph0] = tanh_fast(f0 + xp0 + bb0);
        buf[q][mstar][ph1] = tanh_fast(f1 + xp1 + bb1);

        if (loader) *(float4*)&xps[q][xr][c4] = xn;

        __syncthreads();
        p = q;
    }

    // final projection
    if (tid < ROWS * ODIM) {
        const int m = tid / ODIM;
        const int j = tid % ODIM;
        float s = b_ph[j];
#pragma unroll 4
        for (int k = 0; k < HDIM; k++)
            s += buf[p][m][physh(k)] * W_ph[j * HDIM + k];
        out[(size_t)(b0r + m) * ODIM + j] = s;
    }
}

extern "C" void kernel_launch(void* const* d_in, const int* in_sizes, int n_in,
                              void* d_out, int out_size) {
    const float* x    = (const float*)d_in[0];
    const float* W_hx = (const float*)d_in[1];
    const float* W_hh = (const float*)d_in[2];
    const float* b_hh = (const float*)d_in[3];
    const float* W_ph = (const float*)d_in[4];
    const float* b_ph = (const float*)d_in[5];
    float* out = (float*)d_out;

    xproj_kernel<<<K1_GRID, 256>>>(x, W_hx);
    rnn_fused_kernel<<<GRID, NTHREADS>>>(W_hh, b_hh, W_ph, b_ph, out);
}